// round 2
// baseline (speedup 1.0000x reference)
#include <cuda_runtime.h>
#include <math.h>

#define T_LEN   8192
#define BATCH   16
#define HID     256
#define DIN     7

#define NA      32            // layer-0 CTAs (8 h-dims each)
#define NB      64            // layer-1 CTAs (4 h-dims each)
#define GRID_SZ (NA + NB + 1) // + 1 head CTA
#define NTHR    512
#define SSTEPS  (T_LEN + 2)   // pipeline drain: layer1 lags 1, head lags 2

#define HPAD    260
#define INPAD   516

#define OUT_ELEMS (BATCH * T_LEN * DIN)            // 917504
#define HN_OFF    OUT_ELEMS
#define CN_OFF    (OUT_ELEMS + 2 * BATCH * HID)

// Max smem: role B = (16*512 + 16 + 16*516 + 512 + 64) floats = 17040*4 = 68160 B
#define SMEM_BYTES 68160

__device__ unsigned g_bar;                       // monotonic barrier counter (reset at end of run)
__device__ float g_h0[2][BATCH][HID];            // layer0 h ring
__device__ float g_h1[2][BATCH][HID];            // layer1 h ring

typedef unsigned long long ull;

__device__ __forceinline__ ull pk2(float a, float b) {
    ull r; asm("mov.b64 %0, {%1,%2};" : "=l"(r) : "f"(a), "f"(b)); return r;
}
__device__ __forceinline__ void fma2(ull& acc, ull a, ull b) {
    asm("fma.rn.f32x2 %0, %1, %2, %0;" : "+l"(acc) : "l"(a), "l"(b));
}
__device__ __forceinline__ float hsum2(ull a) {
    float x, y; asm("mov.b64 {%0,%1}, %2;" : "=f"(x), "=f"(y) : "l"(a)); return x + y;
}
__device__ __forceinline__ float sigf(float x) { return 1.0f / (1.0f + expf(-x)); }

// grid barrier: release-arrive + acquire-spin on a monotonic counter
__device__ __forceinline__ void gbar(unsigned target) {
    __syncthreads();
    if (threadIdx.x == 0) {
        __threadfence();
        atomicAdd(&g_bar, 1u);
        unsigned v;
        do {
            asm volatile("ld.acquire.gpu.u32 %0, [%1];" : "=r"(v) : "l"(&g_bar));
        } while (v < target);
    }
    __syncthreads();
}

// 256-length dot product, f32x2 packed FMA, LDS.128 operands (both 16B-aligned)
__device__ __forceinline__ float dot256(const float* __restrict__ w, const float* __restrict__ h) {
    ull acc = 0ull;  // (0.0f, 0.0f)
#pragma unroll 8
    for (int k = 0; k < 256; k += 4) {
        float4 wv = *reinterpret_cast<const float4*>(w + k);
        float4 hv = *reinterpret_cast<const float4*>(h + k);
        fma2(acc, pk2(wv.x, wv.y), pk2(hv.x, hv.y));
        fma2(acc, pk2(wv.z, wv.w), pk2(hv.z, hv.w));
    }
    return hsum2(acc);
}

extern __shared__ float smem[];

__global__ void __launch_bounds__(NTHR, 1) lstm_persistent_kernel(
    const float* __restrict__ x,
    const float* __restrict__ W_ih0, const float* __restrict__ W_hh0, const float* __restrict__ b0,
    const float* __restrict__ W_ih1, const float* __restrict__ W_hh1, const float* __restrict__ b1,
    const float* __restrict__ W_head, const float* __restrict__ b_head,
    float* __restrict__ out)
{
    const int tid = threadIdx.x;
    const int cta = blockIdx.x;

    if (cta < NA) {
        // ------------------------- Layer 0 CTA: 8 h-dims, 32 gate rows -------------------------
        float* Ws  = smem;               // [32][256]
        float* Wx  = Ws + 32 * 256;      // [32][8] (x-projection slice, padded)
        float* bs  = Wx + 32 * 8;        // [32]
        float* hs  = bs + 32;            // [16][HPAD]   (offset 8480 floats, 16B aligned)
        float* xs  = hs + 16 * HPAD;     // [16][8]
        float* gsm = xs + 16 * 8;        // [32][16]
        float* csm = gsm + 32 * 16;      // [8][16]
        const int base = cta * 8;

        for (int idx = tid; idx < 32 * 256; idx += NTHR) {
            int r = idx >> 8, k = idx & 255;
            int grow = (r >> 3) * 256 + base + (r & 7);   // gate-major: i,f,g,o blocks of 256
            Ws[idx] = W_hh0[grow * 256 + k];
        }
        for (int idx = tid; idx < 32 * 8; idx += NTHR) {
            int r = idx >> 3, d = idx & 7;
            int grow = (r >> 3) * 256 + base + (r & 7);
            Wx[idx] = (d < DIN) ? W_ih0[grow * DIN + d] : 0.0f;
        }
        if (tid < 32) {
            int grow = (tid >> 3) * 256 + base + (tid & 7);
            bs[tid] = b0[grow];
        }
        if (tid < 128) csm[tid] = 0.0f;

        const int r = tid >> 4, b = tid & 15;

        for (int s = 0; s < SSTEPS; ++s) {
            if (s < T_LEN) {
                // stage h_{s-1} (L1-bypassed; ring slot reuse makes L1 stale) and x_s
                if (s == 0) {
                    for (int i = tid; i < BATCH * HID; i += NTHR)
                        hs[(i >> 8) * HPAD + (i & 255)] = 0.0f;
                } else {
                    const float* src = &g_h0[(s - 1) & 1][0][0];
                    for (int i = tid; i < BATCH * HID; i += NTHR)
                        hs[(i >> 8) * HPAD + (i & 255)] = __ldcg(src + i);
                }
                if (tid < BATCH * DIN) {
                    int bb = tid / DIN, d = tid - bb * DIN;
                    xs[bb * 8 + d] = __ldg(&x[(bb * T_LEN + s) * DIN + d]);
                }
                __syncthreads();

                float sum = dot256(Ws + r * 256, hs + b * HPAD);
#pragma unroll
                for (int d = 0; d < DIN; ++d) sum += Wx[r * 8 + d] * xs[b * 8 + d];
                sum += bs[r];
                gsm[r * 16 + b] = sum;
                __syncthreads();

                if (tid < 128) {
                    int dl = tid >> 4, bb = tid & 15;
                    float iv = gsm[dl * 16 + bb];
                    float fv = gsm[(8  + dl) * 16 + bb];
                    float gv = gsm[(16 + dl) * 16 + bb];
                    float ov = gsm[(24 + dl) * 16 + bb];
                    float c  = csm[dl * 16 + bb];
                    float cn = sigf(fv) * c + sigf(iv) * tanhf(gv);
                    float hn = sigf(ov) * tanhf(cn);
                    csm[dl * 16 + bb] = cn;
                    g_h0[s & 1][bb][base + dl] = hn;
                    if (s == T_LEN - 1) {
                        out[HN_OFF + bb * HID + base + dl] = hn;
                        out[CN_OFF + bb * HID + base + dl] = cn;
                    }
                }
            }
            gbar((unsigned)(s + 1) * GRID_SZ);
        }
    } else if (cta < NA + NB) {
        // ------------------------- Layer 1 CTA: 4 h-dims, 16 gate rows, K=512 -------------------------
        float* Ws   = smem;               // [16][512]  (W_ih1 || W_hh1 per row)
        float* bs   = Ws + 16 * 512;      // [16]
        float* in_s = bs + 16;            // [16][INPAD] ([y0 ; h1]; offset 8208 floats, 16B aligned)
        float* gsm  = in_s + 16 * INPAD;  // [2][16][16] (K-half partials)
        float* csm  = gsm + 512;          // [4][16]
        const int base = (cta - NA) * 4;

        for (int idx = tid; idx < 16 * 512; idx += NTHR) {
            int rr = idx >> 9, k = idx & 511;
            int grow = (rr >> 2) * 256 + base + (rr & 3);
            Ws[idx] = (k < 256) ? W_ih1[grow * 256 + k] : W_hh1[grow * 256 + (k - 256)];
        }
        if (tid < 16) {
            int grow = (tid >> 2) * 256 + base + (tid & 3);
            bs[tid] = b1[grow];
        }
        if (tid < 64) csm[tid] = 0.0f;

        const int half = tid >> 8, rr = (tid >> 4) & 15, b = tid & 15;

        for (int s = 0; s < SSTEPS; ++s) {
            if (s >= 1 && s <= T_LEN) {
                const int t1 = s - 1;
                {   // y0_{t1} = h0_{s-1} (written last step); h1_{t1-1}
                    const float* src0 = &g_h0[(s - 1) & 1][0][0];
                    for (int i = tid; i < BATCH * HID; i += NTHR)
                        in_s[(i >> 8) * INPAD + (i & 255)] = __ldcg(src0 + i);
                    if (t1 == 0) {
                        for (int i = tid; i < BATCH * HID; i += NTHR)
                            in_s[(i >> 8) * INPAD + 256 + (i & 255)] = 0.0f;
                    } else {
                        const float* src1 = &g_h1[(s - 2) & 1][0][0];
                        for (int i = tid; i < BATCH * HID; i += NTHR)
                            in_s[(i >> 8) * INPAD + 256 + (i & 255)] = __ldcg(src1 + i);
                    }
                }
                __syncthreads();

                float sum = dot256(Ws + rr * 512 + half * 256, in_s + b * INPAD + half * 256);
                gsm[half * 256 + rr * 16 + b] = sum;
                __syncthreads();

                if (tid < 64) {
                    int dl = tid >> 4, bb = tid & 15;
                    float iv = gsm[dl * 16 + bb]        + gsm[256 + dl * 16 + bb]        + bs[dl];
                    float fv = gsm[(4 + dl) * 16 + bb]  + gsm[256 + (4 + dl) * 16 + bb]  + bs[4 + dl];
                    float gv = gsm[(8 + dl) * 16 + bb]  + gsm[256 + (8 + dl) * 16 + bb]  + bs[8 + dl];
                    float ov = gsm[(12 + dl) * 16 + bb] + gsm[256 + (12 + dl) * 16 + bb] + bs[12 + dl];
                    float c  = csm[dl * 16 + bb];
                    float cn = sigf(fv) * c + sigf(iv) * tanhf(gv);
                    float hn = sigf(ov) * tanhf(cn);
                    csm[dl * 16 + bb] = cn;
                    g_h1[t1 & 1][bb][base + dl] = hn;
                    if (t1 == T_LEN - 1) {
                        out[HN_OFF + BATCH * HID + bb * HID + base + dl] = hn;
                        out[CN_OFF + BATCH * HID + bb * HID + base + dl] = cn;
                    }
                }
            }
            gbar((unsigned)(s + 1) * GRID_SZ);
        }
    } else {
        // ------------------------- Head CTA: out_t = W_head @ h1_t + b_head, lags 2 steps -------------------------
        float* Wh  = smem;            // [7][256]
        float* bh  = Wh + 1792;       // [16] padded
        float* h1s = bh + 16;         // [16][HPAD]  (offset 1808 floats, 16B aligned)

        for (int idx = tid; idx < DIN * 256; idx += NTHR) Wh[idx] = W_head[idx];
        if (tid < DIN) bh[tid] = b_head[tid];

        for (int s = 0; s < SSTEPS; ++s) {
            if (s >= 2) {
                const int t = s - 2;
                const float* src = &g_h1[t & 1][0][0];
                for (int i = tid; i < BATCH * HID; i += NTHR)
                    h1s[(i >> 8) * HPAD + (i & 255)] = __ldcg(src + i);
                __syncthreads();
                if (tid < BATCH * DIN) {
                    int bb = tid / DIN, d = tid - bb * DIN;
                    float sum = dot256(Wh + d * 256, h1s + bb * HPAD) + bh[d];
                    out[(bb * T_LEN + t) * DIN + d] = sum;
                }
            }
            gbar((unsigned)(s + 1) * GRID_SZ);
        }
    }

    // Reset barrier counter for the next graph replay: everyone arrives once more,
    // CTA 0 waits for all arrivals, then zeroes the counter.
    if (threadIdx.x == 0) {
        __threadfence();
        atomicAdd(&g_bar, 1u);
        if (cta == 0) {
            const unsigned target = (unsigned)SSTEPS * GRID_SZ + GRID_SZ;
            unsigned v;
            do {
                asm volatile("ld.acquire.gpu.u32 %0, [%1];" : "=r"(v) : "l"(&g_bar));
            } while (v < target);
            atomicExch(&g_bar, 0u);
        }
    }
}

extern "C" void kernel_launch(void* const* d_in, const int* in_sizes, int n_in,
                              void* d_out, int out_size) {
    const float* x      = (const float*)d_in[0];
    const float* W_ih0  = (const float*)d_in[1];
    const float* W_hh0  = (const float*)d_in[2];
    const float* b0     = (const float*)d_in[3];
    const float* W_ih1  = (const float*)d_in[4];
    const float* W_hh1  = (const float*)d_in[5];
    const float* b1     = (const float*)d_in[6];
    const float* W_head = (const float*)d_in[7];
    const float* b_head = (const float*)d_in[8];

    cudaFuncSetAttribute(lstm_persistent_kernel,
                         cudaFuncAttributeMaxDynamicSharedMemorySize, SMEM_BYTES);

    lstm_persistent_kernel<<<GRID_SZ, NTHR, SMEM_BYTES>>>(
        x, W_ih0, W_hh0, b0, W_ih1, W_hh1, b1, W_head, b_head, (float*)d_out);
}

// round 3
// speedup vs baseline: 1.0334x; 1.0334x over previous
#include <cuda_runtime.h>
#include <math.h>

#define T_LEN   8192
#define BATCH   16
#define HID     256
#define DIN     7

#define NA      32            // layer-0 CTAs (8 h-dims -> 32 gate rows each)
#define NB      64            // layer-1 CTAs (4 h-dims -> 16 gate rows each, K=512)
#define GRID_SZ (NA + NB + 1) // + 1 head CTA
#define NTHR    512
#define SSTEPS  (T_LEN + 2)   // pipeline drain: layer1 lags 1, head lags 2

#define OUT_ELEMS (BATCH * T_LEN * DIN)
#define HN_OFF    OUT_ELEMS
#define CN_OFF    (OUT_ELEMS + 2 * BATCH * HID)

// Layer1 smem: in_s 16*520 + part 8*16*17 + gsm2 16*17 + bs 16 + csm 64 = 10848 floats
#define SMEM_BYTES 43520

__device__ unsigned g_bar;
__device__ float g_h0[2][BATCH][HID];
__device__ float g_h1[2][BATCH][HID];

typedef unsigned long long ull;

__device__ __forceinline__ ull pk2(float a, float b) {
    ull r; asm("mov.b64 %0, {%1,%2};" : "=l"(r) : "f"(a), "f"(b)); return r;
}
__device__ __forceinline__ void fma2(ull& acc, ull a, ull b) {
    asm("fma.rn.f32x2 %0, %1, %2, %0;" : "+l"(acc) : "l"(a), "l"(b));
}
__device__ __forceinline__ float hsum2(ull a) {
    float x, y; asm("mov.b64 {%0,%1}, %2;" : "=f"(x), "=f"(y) : "l"(a)); return x + y;
}
__device__ __forceinline__ float sigf(float x) { return 1.0f / (1.0f + expf(-x)); }

__device__ __forceinline__ void gbar(unsigned target) {
    __syncthreads();
    if (threadIdx.x == 0) {
        __threadfence();
        atomicAdd(&g_bar, 1u);
        unsigned v;
        do {
            asm volatile("ld.acquire.gpu.u32 %0, [%1];" : "=r"(v) : "l"(&g_bar));
        } while (v < target);
    }
    __syncthreads();
}

// 64-float dot: weights in registers (32 x f32x2), h from smem (16B-aligned).
__device__ __forceinline__ float dot64_reg(const ull* __restrict__ Wreg,
                                           const float* __restrict__ hp) {
    const ulonglong2* h2 = reinterpret_cast<const ulonglong2*>(hp);
    ull a0 = 0ull, a1 = 0ull;
#pragma unroll
    for (int i = 0; i < 16; ++i) {
        ulonglong2 hv = h2[i];
        fma2(a0, Wreg[2 * i],     hv.x);
        fma2(a1, Wreg[2 * i + 1], hv.y);
    }
    return hsum2(a0) + hsum2(a1);
}

// head-only: 256-float dot, both operands smem
__device__ __forceinline__ float dot256s(const float* __restrict__ w, const float* __restrict__ h) {
    ull acc = 0ull;
#pragma unroll 8
    for (int k = 0; k < 256; k += 4) {
        float4 wv = *reinterpret_cast<const float4*>(w + k);
        float4 hv = *reinterpret_cast<const float4*>(h + k);
        fma2(acc, pk2(wv.x, wv.y), pk2(hv.x, hv.y));
        fma2(acc, pk2(wv.z, wv.w), pk2(hv.z, hv.w));
    }
    return hsum2(acc);
}

extern __shared__ float smem[];

__global__ void __launch_bounds__(NTHR, 1) lstm_persistent_kernel(
    const float* __restrict__ x,
    const float* __restrict__ W_ih0, const float* __restrict__ W_hh0, const float* __restrict__ b0,
    const float* __restrict__ W_ih1, const float* __restrict__ W_hh1, const float* __restrict__ b1,
    const float* __restrict__ W_head, const float* __restrict__ b_head,
    float* __restrict__ out)
{
    const int tid  = threadIdx.x;
    const int cta  = blockIdx.x;
    const int lane = tid & 31;
    const int wrp  = tid >> 5;

    if (cta < NA) {
        // ---------------- Layer 0 CTA: 32 gate rows, K=256, weights in regs ----------------
        // warp: q = wrp & 3 (k-quarter), bg = wrp >> 2 (batch group of 4). lane = gate row r.
        float* hs   = smem;                 // [16][256] flat copy of h ring (broadcast reads)
        float* part = hs + 16 * 256;        // [4 q][16 b][33] padded partials
        float* Wx   = part + 4 * 16 * 33;   // [32][8]
        float* xs   = Wx + 32 * 8;          // [16][8]
        float* bs   = xs + 16 * 8;          // [32]
        float* csm  = bs + 32;              // [8][16]
        const int base = cta * 8;
        const int q = wrp & 3, bg = wrp >> 2;
        const int r = lane;                          // 0..31
        const int grow = (r >> 3) * 256 + base + (r & 7);

        // weights -> registers (once)
        ull Wreg[32];
        {
            const float4* wp = reinterpret_cast<const float4*>(W_hh0 + grow * 256 + q * 64);
#pragma unroll
            for (int j = 0; j < 16; ++j) {
                float4 wv = __ldg(wp + j);
                Wreg[2 * j]     = pk2(wv.x, wv.y);
                Wreg[2 * j + 1] = pk2(wv.z, wv.w);
            }
        }
        for (int idx = tid; idx < 32 * 8; idx += NTHR) {
            int rr = idx >> 3, d = idx & 7;
            int gr = (rr >> 3) * 256 + base + (rr & 7);
            Wx[idx] = (d < DIN) ? W_ih0[gr * DIN + d] : 0.0f;
        }
        if (tid < 32) bs[tid] = b0[grow];            // tid==r mapping holds for tid<32
        if (tid < 128) csm[tid] = 0.0f;

        for (int s = 0; s < SSTEPS; ++s) {
            if (s < T_LEN) {
                if (s == 0) {
                    for (int i = tid; i < BATCH * HID; i += NTHR) hs[i] = 0.0f;
                } else {
                    const float* src = &g_h0[(s - 1) & 1][0][0];
                    for (int i = tid; i < BATCH * HID; i += NTHR) hs[i] = __ldcg(src + i);
                }
                if (tid < BATCH * DIN) {
                    int bb = tid / DIN, d = tid - bb * DIN;
                    xs[bb * 8 + d] = __ldg(&x[(bb * T_LEN + s) * DIN + d]);
                }
                __syncthreads();

#pragma unroll
                for (int it = 0; it < 4; ++it) {
                    int b = bg * 4 + it;
                    float p = dot64_reg(Wreg, hs + b * 256 + q * 64);
                    part[(q * 16 + b) * 33 + r] = p;
                }
                __syncthreads();

                if (tid < 128) {
                    int dl = tid >> 4, bb = tid & 15;
                    float g4[4];
#pragma unroll
                    for (int gate = 0; gate < 4; ++gate) {
                        int rr = gate * 8 + dl;
                        float sum = bs[rr];
#pragma unroll
                        for (int qq = 0; qq < 4; ++qq)
                            sum += part[(qq * 16 + bb) * 33 + rr];
#pragma unroll
                        for (int d = 0; d < DIN; ++d)
                            sum += Wx[rr * 8 + d] * xs[bb * 8 + d];
                        g4[gate] = sum;
                    }
                    float c  = csm[dl * 16 + bb];
                    float cn = sigf(g4[1]) * c + sigf(g4[0]) * tanhf(g4[2]);
                    float hn = sigf(g4[3]) * tanhf(cn);
                    csm[dl * 16 + bb] = cn;
                    g_h0[s & 1][bb][base + dl] = hn;
                    if (s == T_LEN - 1) {
                        out[HN_OFF + bb * HID + base + dl] = hn;
                        out[CN_OFF + bb * HID + base + dl] = cn;
                    }
                }
            }
            gbar((unsigned)(s + 1) * GRID_SZ);
        }
    } else if (cta < NA + NB) {
        // ---------------- Layer 1 CTA: 16 gate rows, K=512, weights in regs ----------------
        // warp: q = wrp & 7 (k-eighth of 64), bq = wrp >> 3. lane: r = lane&15, bh = lane>>4.
        float* in_s = smem;                   // [16][520]  ([y0 ; h1] per batch, padded)
        float* part = in_s + 16 * 520;        // [8 q][16 b][17]
        float* gsm2 = part + 8 * 16 * 17;     // [16 b][17]
        float* bs   = gsm2 + 16 * 17;         // [16]
        float* csm  = bs + 16;                // [4][16]
        const int base = (cta - NA) * 4;
        const int q = wrp & 7, bq = wrp >> 3;
        const int r = lane & 15, bh = lane >> 4;
        const int grow = (r >> 2) * 256 + base + (r & 3);

        ull Wreg[32];
        {
            const float* wrow = (q < 4) ? (W_ih1 + grow * 256 + q * 64)
                                        : (W_hh1 + grow * 256 + (q - 4) * 64);
            const float4* wp = reinterpret_cast<const float4*>(wrow);
#pragma unroll
            for (int j = 0; j < 16; ++j) {
                float4 wv = __ldg(wp + j);
                Wreg[2 * j]     = pk2(wv.x, wv.y);
                Wreg[2 * j + 1] = pk2(wv.z, wv.w);
            }
        }
        if (tid < 16) bs[tid] = b1[(tid >> 2) * 256 + base + (tid & 3)];
        if (tid < 64) csm[tid] = 0.0f;

        for (int s = 0; s < SSTEPS; ++s) {
            if (s >= 1 && s <= T_LEN) {
                const int t1 = s - 1;
                {
                    const float* src0 = &g_h0[(s - 1) & 1][0][0];
                    for (int i = tid; i < BATCH * HID; i += NTHR)
                        in_s[(i >> 8) * 520 + (i & 255)] = __ldcg(src0 + i);
                    if (t1 == 0) {
                        for (int i = tid; i < BATCH * HID; i += NTHR)
                            in_s[(i >> 8) * 520 + 256 + (i & 255)] = 0.0f;
                    } else {
                        const float* src1 = &g_h1[(s - 2) & 1][0][0];
                        for (int i = tid; i < BATCH * HID; i += NTHR)
                            in_s[(i >> 8) * 520 + 256 + (i & 255)] = __ldcg(src1 + i);
                    }
                }
                __syncthreads();

#pragma unroll
                for (int it = 0; it < 4; ++it) {
                    int b = bq * 8 + it * 2 + bh;
                    float p = dot64_reg(Wreg, in_s + b * 520 + q * 64);
                    part[(q * 16 + b) * 17 + r] = p;
                }
                __syncthreads();

                // reduce over 8 q: 256 threads, one (r,b) each
                if (tid < 256) {
                    int rr = tid & 15, bb = tid >> 4;
                    float sum = bs[rr];
#pragma unroll
                    for (int qq = 0; qq < 8; ++qq)
                        sum += part[(qq * 16 + bb) * 17 + rr];
                    gsm2[bb * 17 + rr] = sum;
                }
                __syncthreads();

                if (tid < 64) {
                    int dl = tid >> 4, bb = tid & 15;
                    float iv = gsm2[bb * 17 + dl];
                    float fv = gsm2[bb * 17 + 4 + dl];
                    float gv = gsm2[bb * 17 + 8 + dl];
                    float ov = gsm2[bb * 17 + 12 + dl];
                    float c  = csm[dl * 16 + bb];
                    float cn = sigf(fv) * c + sigf(iv) * tanhf(gv);
                    float hn = sigf(ov) * tanhf(cn);
                    csm[dl * 16 + bb] = cn;
                    g_h1[t1 & 1][bb][base + dl] = hn;
                    if (t1 == T_LEN - 1) {
                        out[HN_OFF + BATCH * HID + bb * HID + base + dl] = hn;
                        out[CN_OFF + BATCH * HID + bb * HID + base + dl] = cn;
                    }
                }
            }
            gbar((unsigned)(s + 1) * GRID_SZ);
        }
    } else {
        // ---------------- Head CTA: out_t = W_head @ h1_t + b_head (lag 2) ----------------
        float* Wh  = smem;            // [7][256]
        float* bh  = Wh + 1792;       // [16]
        float* h1s = bh + 16;         // [16][260]

        for (int idx = tid; idx < DIN * 256; idx += NTHR) Wh[idx] = W_head[idx];
        if (tid < DIN) bh[tid] = b_head[tid];

        for (int s = 0; s < SSTEPS; ++s) {
            if (s >= 2) {
                const int t = s - 2;
                const float* src = &g_h1[t & 1][0][0];
                for (int i = tid; i < BATCH * HID; i += NTHR)
                    h1s[(i >> 8) * 260 + (i & 255)] = __ldcg(src + i);
                __syncthreads();
                if (tid < BATCH * DIN) {
                    int bb = tid / DIN, d = tid - bb * DIN;
                    out[(bb * T_LEN + t) * DIN + d] = dot256s(Wh + d * 256, h1s + bb * 260) + bh[d];
                }
            }
            gbar((unsigned)(s + 1) * GRID_SZ);
        }
    }

    // barrier counter reset for next graph replay
    if (threadIdx.x == 0) {
        __threadfence();
        atomicAdd(&g_bar, 1u);
        if (cta == 0) {
            const unsigned target = (unsigned)SSTEPS * GRID_SZ + GRID_SZ;
            unsigned v;
            do {
                asm volatile("ld.acquire.gpu.u32 %0, [%1];" : "=r"(v) : "l"(&g_bar));
            } while (v < target);
            atomicExch(&g_bar, 0u);
        }
    }
}

extern "C" void kernel_launch(void* const* d_in, const int* in_sizes, int n_in,
                              void* d_out, int out_size) {
    const float* x      = (const float*)d_in[0];
    const float* W_ih0  = (const float*)d_in[1];
    const float* W_hh0  = (const float*)d_in[2];
    const float* b0     = (const float*)d_in[3];
    const float* W_ih1  = (const float*)d_in[4];
    const float* W_hh1  = (const float*)d_in[5];
    const float* b1     = (const float*)d_in[6];
    const float* W_head = (const float*)d_in[7];
    const float* b_head = (const float*)d_in[8];

    cudaFuncSetAttribute(lstm_persistent_kernel,
                         cudaFuncAttributeMaxDynamicSharedMemorySize, SMEM_BYTES);

    lstm_persistent_kernel<<<GRID_SZ, NTHR, SMEM_BYTES>>>(
        x, W_ih0, W_hh0, b0, W_ih1, W_hh1, b1, W_head, b_head, (float*)d_out);
}

// round 4
// speedup vs baseline: 1.0397x; 1.0061x over previous
#include <cuda_runtime.h>
#include <math.h>

#define T_LEN   8192
#define BATCH   16
#define HID     256
#define DIN     7

#define NA      32            // layer-0 CTAs (8 h-dims -> 32 gate rows each)
#define NB      64            // layer-1 CTAs (4 h-dims -> 16 gate rows each, K=512)
#define GRID_SZ (NA + NB + 1) // + 1 head CTA
#define NTHR    512
#define RING    8
#define FPAD    8             // 32B per flag (sector-padded)

#define OUT_ELEMS (BATCH * T_LEN * DIN)
#define HN_OFF    OUT_ELEMS
#define CN_OFF    (OUT_ELEMS + 2 * BATCH * HID)

#define SMEM_BYTES 43520

__device__ unsigned g_bar;                 // end-of-run reset barrier only
__device__ int g_flag0[NA * FPAD];         // layer0 CTA i published h0(s-1) => flag0[i] >= s
__device__ int g_flag1[NB * FPAD];
__device__ int g_flagH[FPAD];
__device__ float g_h0[RING][BATCH][HID];
__device__ float g_h1[RING][BATCH][HID];

typedef unsigned long long ull;

__device__ __forceinline__ ull pk2(float a, float b) {
    ull r; asm("mov.b64 %0, {%1,%2};" : "=l"(r) : "f"(a), "f"(b)); return r;
}
__device__ __forceinline__ void fma2(ull& acc, ull a, ull b) {
    asm("fma.rn.f32x2 %0, %1, %2, %0;" : "+l"(acc) : "l"(a), "l"(b));
}
__device__ __forceinline__ float hsum2(ull a) {
    float x, y; asm("mov.b64 {%0,%1}, %2;" : "=f"(x), "=f"(y) : "l"(a)); return x + y;
}

// fast transcendentals: MUFU EX2/RCP based, rel err ~1e-6
__device__ __forceinline__ float sigf(float x) {
    return __fdividef(1.0f, 1.0f + __expf(-x));
}
__device__ __forceinline__ float tanhfast(float x) {
    float e = __expf(-2.0f * fabsf(x));
    float t = __fdividef(1.0f - e, 1.0f + e);
    return copysignf(t, x);
}

__device__ __forceinline__ int ldacq(const int* p) {
    int v; asm volatile("ld.acquire.gpu.b32 %0, [%1];" : "=r"(v) : "l"(p) : "memory"); return v;
}
__device__ __forceinline__ void strel(int* p, int v) {
    asm volatile("st.release.gpu.b32 [%0], %1;" :: "l"(p), "r"(v) : "memory");
}

// warp-0 collective polls
__device__ __forceinline__ void wait32(const int* flags, int target) {
    const int* p = flags + (threadIdx.x & 31) * FPAD;
    while (__any_sync(0xffffffffu, ldacq(p) < target)) {}
}
__device__ __forceinline__ void wait64(const int* flags, int target) {
    int lane = threadIdx.x & 31;
    const int* p0 = flags + lane * FPAD;
    const int* p1 = flags + (lane + 32) * FPAD;
    while (__any_sync(0xffffffffu, min(ldacq(p0), ldacq(p1)) < target)) {}
}
__device__ __forceinline__ int wait64min(const int* flags, int target) {
    int lane = threadIdx.x & 31;
    const int* p0 = flags + lane * FPAD;
    const int* p1 = flags + (lane + 32) * FPAD;
    int m;
    do { m = min(ldacq(p0), ldacq(p1)); } while (__any_sync(0xffffffffu, m < target));
    return __reduce_min_sync(0xffffffffu, m);
}
__device__ __forceinline__ int wait1(const int* flag, int target) {
    int v;
    do { v = ldacq(flag); } while (__any_sync(0xffffffffu, v < target));
    return v;
}

// 64-float dot: weights in regs (32 x f32x2), h from smem broadcast
__device__ __forceinline__ float dot64_reg(const ull* __restrict__ Wreg,
                                           const float* __restrict__ hp) {
    const ulonglong2* h2 = reinterpret_cast<const ulonglong2*>(hp);
    ull a0 = 0ull, a1 = 0ull;
#pragma unroll
    for (int i = 0; i < 16; ++i) {
        ulonglong2 hv = h2[i];
        fma2(a0, Wreg[2 * i],     hv.x);
        fma2(a1, Wreg[2 * i + 1], hv.y);
    }
    return hsum2(a0) + hsum2(a1);
}

__device__ __forceinline__ float dot256s(const float* __restrict__ w, const float* __restrict__ h) {
    ull acc = 0ull;
#pragma unroll 8
    for (int k = 0; k < 256; k += 4) {
        float4 wv = *reinterpret_cast<const float4*>(w + k);
        float4 hv = *reinterpret_cast<const float4*>(h + k);
        fma2(acc, pk2(wv.x, wv.y), pk2(hv.x, hv.y));
        fma2(acc, pk2(wv.z, wv.w), pk2(hv.z, hv.w));
    }
    return hsum2(acc);
}

extern __shared__ float smem[];

__global__ void __launch_bounds__(NTHR, 1) lstm_persistent_kernel(
    const float* __restrict__ x,
    const float* __restrict__ W_ih0, const float* __restrict__ W_hh0, const float* __restrict__ b0,
    const float* __restrict__ W_ih1, const float* __restrict__ W_hh1, const float* __restrict__ b1,
    const float* __restrict__ W_head, const float* __restrict__ b_head,
    float* __restrict__ out)
{
    const int tid  = threadIdx.x;
    const int cta  = blockIdx.x;
    const int lane = tid & 31;
    const int wrp  = tid >> 5;

    if (cta < NA) {
        // ---------------- Layer 0 CTA: 32 gate rows, K=256, weights in regs ----------------
        float* hs   = smem;                 // [16][256]
        float* part = hs + 16 * 256;        // [4 q][16 b][33]
        float* Wx   = part + 4 * 16 * 33;   // [32][8]
        float* xs   = Wx + 32 * 8;          // [16][8]
        float* bs   = xs + 16 * 8;          // [32]
        float* csm  = bs + 32;              // [8][16]
        const int base = cta * 8;
        const int q = wrp & 3, bg = wrp >> 2;
        const int r = lane;
        const int grow = (r >> 3) * 256 + base + (r & 7);

        ull Wreg[32];
        {
            const float4* wp = reinterpret_cast<const float4*>(W_hh0 + grow * 256 + q * 64);
#pragma unroll
            for (int j = 0; j < 16; ++j) {
                float4 wv = __ldg(wp + j);
                Wreg[2 * j]     = pk2(wv.x, wv.y);
                Wreg[2 * j + 1] = pk2(wv.z, wv.w);
            }
        }
        for (int idx = tid; idx < 32 * 8; idx += NTHR) {
            int rr = idx >> 3, d = idx & 7;
            int gr = (rr >> 3) * 256 + base + (rr & 7);
            Wx[idx] = (d < DIN) ? W_ih0[gr * DIN + d] : 0.0f;
        }
        if (tid < 32) bs[tid] = b0[grow];
        if (tid < 128) csm[tid] = 0.0f;
        __syncthreads();

        int bp1 = RING - 1;   // backpressure cache vs layer1 consumption of h0 ring

        for (int s = 0; s < T_LEN; ++s) {
            // x prefetch (independent of flags -> hides LDG latency behind poll)
            if (tid < BATCH * DIN) {
                int bb = tid / DIN, d = tid - bb * DIN;
                xs[bb * 8 + d] = __ldg(&x[(bb * T_LEN + s) * DIN + d]);
            }
            if (wrp == 0) {
                if (s > 0) wait32(g_flag0, s);
                if (s > bp1) { int m = wait64min(g_flag1, s - (RING - 1)); bp1 = m + (RING - 1); }
            }
            __syncthreads();

            if (s == 0) {
                for (int i = tid; i < 1024; i += NTHR)
                    *reinterpret_cast<float4*>(hs + i * 4) = make_float4(0.f, 0.f, 0.f, 0.f);
            } else {
                const float4* src = reinterpret_cast<const float4*>(&g_h0[(s - 1) & (RING - 1)][0][0]);
                for (int i = tid; i < 1024; i += NTHR)
                    *reinterpret_cast<float4*>(hs + i * 4) = __ldcg(src + i);
            }
            __syncthreads();

#pragma unroll
            for (int it = 0; it < 4; ++it) {
                int b = bg * 4 + it;
                part[(q * 16 + b) * 33 + r] = dot64_reg(Wreg, hs + b * 256 + q * 64);
            }
            __syncthreads();

            if (tid < 128) {
                int dl = tid >> 4, bb = tid & 15;
                float g4[4];
#pragma unroll
                for (int gate = 0; gate < 4; ++gate) {
                    int rr = gate * 8 + dl;
                    float sum = bs[rr];
#pragma unroll
                    for (int qq = 0; qq < 4; ++qq) sum += part[(qq * 16 + bb) * 33 + rr];
#pragma unroll
                    for (int d = 0; d < DIN; ++d) sum += Wx[rr * 8 + d] * xs[bb * 8 + d];
                    g4[gate] = sum;
                }
                float c  = csm[dl * 16 + bb];
                float cn = sigf(g4[1]) * c + sigf(g4[0]) * tanhfast(g4[2]);
                float hn = sigf(g4[3]) * tanhfast(cn);
                csm[dl * 16 + bb] = cn;
                g_h0[s & (RING - 1)][bb][base + dl] = hn;
                if (s == T_LEN - 1) {
                    out[HN_OFF + bb * HID + base + dl] = hn;
                    out[CN_OFF + bb * HID + base + dl] = cn;
                }
            }
            __syncthreads();
            if (tid == 0) strel(&g_flag0[cta * FPAD], s + 1);
        }
    } else if (cta < NA + NB) {
        // ---------------- Layer 1 CTA: 16 gate rows, K=512, weights in regs ----------------
        float* in_s = smem;                   // [16][520]
        float* part = in_s + 16 * 520;        // [8 q][16 b][17]
        float* gsm2 = part + 8 * 16 * 17;     // [16 b][17]
        float* bs   = gsm2 + 16 * 17;         // [16]
        float* csm  = bs + 16;                // [4][16]
        const int base = (cta - NA) * 4;
        const int q = wrp & 7, bq = wrp >> 3;
        const int r = lane & 15, bh = lane >> 4;
        const int grow = (r >> 2) * 256 + base + (r & 3);

        ull Wreg[32];
        {
            const float* wrow = (q < 4) ? (W_ih1 + grow * 256 + q * 64)
                                        : (W_hh1 + grow * 256 + (q - 4) * 64);
            const float4* wp = reinterpret_cast<const float4*>(wrow);
#pragma unroll
            for (int j = 0; j < 16; ++j) {
                float4 wv = __ldg(wp + j);
                Wreg[2 * j]     = pk2(wv.x, wv.y);
                Wreg[2 * j + 1] = pk2(wv.z, wv.w);
            }
        }
        if (tid < 16) bs[tid] = b1[(tid >> 2) * 256 + base + (tid & 3)];
        if (tid < 64) csm[tid] = 0.0f;
        __syncthreads();

        int bpH = RING - 1;   // backpressure cache vs head consumption of h1 ring

        for (int t1 = 0; t1 < T_LEN; ++t1) {
            if (wrp == 0) {
                if (t1 > 0) wait64(g_flag1, t1);           // peers' h1(t1-1)
                wait32(g_flag0, t1 + 1);                   // h0(t1) available
                if (t1 > bpH) { int m = wait1(g_flagH, t1 - (RING - 1)); bpH = m + (RING - 1); }
            }
            __syncthreads();

            {   // stage [y0(t1) ; h1(t1-1)]
                const float4* src0 = reinterpret_cast<const float4*>(&g_h0[t1 & (RING - 1)][0][0]);
                for (int i = tid; i < 1024; i += NTHR) {
                    int bb = i >> 6, c4 = i & 63;
                    *reinterpret_cast<float4*>(in_s + bb * 520 + c4 * 4) = __ldcg(src0 + i);
                }
                if (t1 == 0) {
                    for (int i = tid; i < 1024; i += NTHR) {
                        int bb = i >> 6, c4 = i & 63;
                        *reinterpret_cast<float4*>(in_s + bb * 520 + 256 + c4 * 4) =
                            make_float4(0.f, 0.f, 0.f, 0.f);
                    }
                } else {
                    const float4* src1 = reinterpret_cast<const float4*>(&g_h1[(t1 - 1) & (RING - 1)][0][0]);
                    for (int i = tid; i < 1024; i += NTHR) {
                        int bb = i >> 6, c4 = i & 63;
                        *reinterpret_cast<float4*>(in_s + bb * 520 + 256 + c4 * 4) = __ldcg(src1 + i);
                    }
                }
            }
            __syncthreads();

#pragma unroll
            for (int it = 0; it < 4; ++it) {
                int b = bq * 8 + it * 2 + bh;
                part[(q * 16 + b) * 17 + r] = dot64_reg(Wreg, in_s + b * 520 + q * 64);
            }
            __syncthreads();

            if (tid < 256) {
                int rr = tid & 15, bb = tid >> 4;
                float sum = bs[rr];
#pragma unroll
                for (int qq = 0; qq < 8; ++qq) sum += part[(qq * 16 + bb) * 17 + rr];
                gsm2[bb * 17 + rr] = sum;
            }
            __syncthreads();

            if (tid < 64) {
                int dl = tid >> 4, bb = tid & 15;
                float iv = gsm2[bb * 17 + dl];
                float fv = gsm2[bb * 17 + 4 + dl];
                float gv = gsm2[bb * 17 + 8 + dl];
                float ov = gsm2[bb * 17 + 12 + dl];
                float c  = csm[dl * 16 + bb];
                float cn = sigf(fv) * c + sigf(iv) * tanhfast(gv);
                float hn = sigf(ov) * tanhfast(cn);
                csm[dl * 16 + bb] = cn;
                g_h1[t1 & (RING - 1)][bb][base + dl] = hn;
                if (t1 == T_LEN - 1) {
                    out[HN_OFF + BATCH * HID + bb * HID + base + dl] = hn;
                    out[CN_OFF + BATCH * HID + bb * HID + base + dl] = cn;
                }
            }
            __syncthreads();
            if (tid == 0) strel(&g_flag1[(cta - NA) * FPAD], t1 + 1);
        }
    } else {
        // ---------------- Head CTA: out_t = W_head @ h1_t + b_head ----------------
        float* Wh  = smem;            // [7][256]
        float* bh  = Wh + 1792;       // [16]
        float* h1s = bh + 16;         // [16][260]

        for (int idx = tid; idx < DIN * 256; idx += NTHR) Wh[idx] = W_head[idx];
        if (tid < DIN) bh[tid] = b_head[tid];
        __syncthreads();

        for (int t = 0; t < T_LEN; ++t) {
            if (wrp == 0) wait64(g_flag1, t + 1);
            __syncthreads();
            const float4* src = reinterpret_cast<const float4*>(&g_h1[t & (RING - 1)][0][0]);
            for (int i = tid; i < 1024; i += NTHR) {
                int bb = i >> 6, c4 = i & 63;
                *reinterpret_cast<float4*>(h1s + bb * 260 + c4 * 4) = __ldcg(src + i);
            }
            __syncthreads();
            if (tid == 0) strel(&g_flagH[0], t + 1);   // h1(t) consumed
            if (tid < BATCH * DIN) {
                int bb = tid / DIN, d = tid - bb * DIN;
                out[(bb * T_LEN + t) * DIN + d] = dot256s(Wh + d * 256, h1s + bb * 260) + bh[d];
            }
        }
    }

    // ---- end-of-run reset: two-phase barrier, each CTA zeroes its own flags ----
    __syncthreads();
    if (tid == 0) {
        __threadfence();
        atomicAdd(&g_bar, 1u);
        unsigned v;
        do { asm volatile("ld.acquire.gpu.u32 %0, [%1];" : "=r"(v) : "l"(&g_bar)); } while (v < GRID_SZ);
        if (cta < NA)            g_flag0[cta * FPAD] = 0;
        else if (cta < NA + NB)  g_flag1[(cta - NA) * FPAD] = 0;
        else                     g_flagH[0] = 0;
        __threadfence();
        atomicAdd(&g_bar, 1u);
        if (cta == 0) {
            do { asm volatile("ld.acquire.gpu.u32 %0, [%1];" : "=r"(v) : "l"(&g_bar)); } while (v < 2u * GRID_SZ);
            atomicExch(&g_bar, 0u);
        }
    }
}

extern "C" void kernel_launch(void* const* d_in, const int* in_sizes, int n_in,
                              void* d_out, int out_size) {
    const float* x      = (const float*)d_in[0];
    const float* W_ih0  = (const float*)d_in[1];
    const float* W_hh0  = (const float*)d_in[2];
    const float* b0     = (const float*)d_in[3];
    const float* W_ih1  = (const float*)d_in[4];
    const float* W_hh1  = (const float*)d_in[5];
    const float* b1     = (const float*)d_in[6];
    const float* W_head = (const float*)d_in[7];
    const float* b_head = (const float*)d_in[8];

    cudaFuncSetAttribute(lstm_persistent_kernel,
                         cudaFuncAttributeMaxDynamicSharedMemorySize, SMEM_BYTES);

    lstm_persistent_kernel<<<GRID_SZ, NTHR, SMEM_BYTES>>>(
        x, W_ih0, W_hh0, b0, W_ih1, W_hh1, b1, W_head, b_head, (float*)d_out);
}

// round 5
// speedup vs baseline: 1.0509x; 1.0107x over previous
#include <cuda_runtime.h>
#include <math.h>

#define T_LEN   8192
#define BATCH   16
#define HID     256
#define DIN     7

#define NA      32            // layer-0 CTAs (8 h-dims -> 32 gate rows each)
#define NB      64            // layer-1 CTAs (4 h-dims -> 16 gate rows each, K=512)
#define GRID_SZ (NA + NB + 1) // + 1 head CTA
#define NTHR    512
#define RING    8
#define FPAD    8             // 32B per flag (sector-padded)

#define OUT_ELEMS (BATCH * T_LEN * DIN)
#define HN_OFF    OUT_ELEMS
#define CN_OFF    (OUT_ELEMS + 2 * BATCH * HID)

#define SMEM_BYTES 43520

__device__ unsigned g_bar;                 // end-of-run reset barrier only
__device__ int g_flag0[NA * FPAD];         // layer0 CTA i published h0(s-1) => flag0[i] >= s
__device__ int g_flag1[NB * FPAD];
__device__ int g_flagH[FPAD];
__device__ float g_h0[RING][BATCH][HID];
__device__ float g_h1[RING][BATCH][HID];

typedef unsigned long long ull;

__device__ __forceinline__ ull pk2(float a, float b) {
    ull r; asm("mov.b64 %0, {%1,%2};" : "=l"(r) : "f"(a), "f"(b)); return r;
}
__device__ __forceinline__ void fma2(ull& acc, ull a, ull b) {
    asm("fma.rn.f32x2 %0, %1, %2, %0;" : "+l"(acc) : "l"(a), "l"(b));
}
__device__ __forceinline__ float hsum2(ull a) {
    float x, y; asm("mov.b64 {%0,%1}, %2;" : "=f"(x), "=f"(y) : "l"(a)); return x + y;
}

// fast transcendentals: MUFU EX2/RCP based, rel err ~1e-6
__device__ __forceinline__ float sigf(float x) {
    return __fdividef(1.0f, 1.0f + __expf(-x));
}
__device__ __forceinline__ float tanhfast(float x) {
    float e = __expf(-2.0f * fabsf(x));
    float t = __fdividef(1.0f - e, 1.0f + e);
    return copysignf(t, x);
}

__device__ __forceinline__ int ldacq(const int* p) {
    int v; asm volatile("ld.acquire.gpu.b32 %0, [%1];" : "=r"(v) : "l"(p) : "memory"); return v;
}
__device__ __forceinline__ void strel(int* p, int v) {
    asm volatile("st.release.gpu.b32 [%0], %1;" :: "l"(p), "r"(v) : "memory");
}

// warp-0 collective polls
__device__ __forceinline__ void wait32(const int* flags, int target) {
    const int* p = flags + (threadIdx.x & 31) * FPAD;
    while (__any_sync(0xffffffffu, ldacq(p) < target)) {}
}
__device__ __forceinline__ void wait64(const int* flags, int target) {
    int lane = threadIdx.x & 31;
    const int* p0 = flags + lane * FPAD;
    const int* p1 = flags + (lane + 32) * FPAD;
    while (__any_sync(0xffffffffu, min(ldacq(p0), ldacq(p1)) < target)) {}
}
__device__ __forceinline__ int wait64min(const int* flags, int target) {
    int lane = threadIdx.x & 31;
    const int* p0 = flags + lane * FPAD;
    const int* p1 = flags + (lane + 32) * FPAD;
    int m;
    do { m = min(ldacq(p0), ldacq(p1)); } while (__any_sync(0xffffffffu, m < target));
    return __reduce_min_sync(0xffffffffu, m);
}
__device__ __forceinline__ int wait1(const int* flag, int target) {
    int v;
    do { v = ldacq(flag); } while (__any_sync(0xffffffffu, v < target));
    return v;
}

// 64-float dot: weights in regs (32 x f32x2), h from smem broadcast
__device__ __forceinline__ float dot64_reg(const ull* __restrict__ Wreg,
                                           const float* __restrict__ hp) {
    const ulonglong2* h2 = reinterpret_cast<const ulonglong2*>(hp);
    ull a0 = 0ull, a1 = 0ull;
#pragma unroll
    for (int i = 0; i < 16; ++i) {
        ulonglong2 hv = h2[i];
        fma2(a0, Wreg[2 * i],     hv.x);
        fma2(a1, Wreg[2 * i + 1], hv.y);
    }
    return hsum2(a0) + hsum2(a1);
}

__device__ __forceinline__ float dot256s(const float* __restrict__ w, const float* __restrict__ h) {
    ull acc = 0ull;
#pragma unroll 8
    for (int k = 0; k < 256; k += 4) {
        float4 wv = *reinterpret_cast<const float4*>(w + k);
        float4 hv = *reinterpret_cast<const float4*>(h + k);
        fma2(acc, pk2(wv.x, wv.y), pk2(hv.x, hv.y));
        fma2(acc, pk2(wv.z, wv.w), pk2(hv.z, hv.w));
    }
    return hsum2(acc);
}

extern __shared__ float smem[];

__global__ void __launch_bounds__(NTHR, 1) lstm_persistent_kernel(
    const float* __restrict__ x,
    const float* __restrict__ W_ih0, const float* __restrict__ W_hh0, const float* __restrict__ b0,
    const float* __restrict__ W_ih1, const float* __restrict__ W_hh1, const float* __restrict__ b1,
    const float* __restrict__ W_head, const float* __restrict__ b_head,
    float* __restrict__ out)
{
    const int tid  = threadIdx.x;
    const int cta  = blockIdx.x;
    const int lane = tid & 31;
    const int wrp  = tid >> 5;

    if (cta < NA) {
        // ---------------- Layer 0 CTA: 32 gate rows, K=256, weights in regs ----------------
        float* hs   = smem;                 // [16][256]
        float* part = hs + 16 * 256;        // [4 q][16 b][33]
        float* Wx   = part + 4 * 16 * 33;   // [32][8]
        float* xs   = Wx + 32 * 8;          // [16][8]
        float* bs   = xs + 16 * 8;          // [32]
        float* csm  = bs + 32;              // [8][16]
        const int base = cta * 8;
        const int q = wrp & 3, bg = wrp >> 2;
        const int r = lane;
        const int grow = (r >> 3) * 256 + base + (r & 7);

        ull Wreg[32];
        {
            const float4* wp = reinterpret_cast<const float4*>(W_hh0 + grow * 256 + q * 64);
#pragma unroll
            for (int j = 0; j < 16; ++j) {
                float4 wv = __ldg(wp + j);
                Wreg[2 * j]     = pk2(wv.x, wv.y);
                Wreg[2 * j + 1] = pk2(wv.z, wv.w);
            }
        }
        for (int idx = tid; idx < 32 * 8; idx += NTHR) {
            int rr = idx >> 3, d = idx & 7;
            int gr = (rr >> 3) * 256 + base + (rr & 7);
            Wx[idx] = (d < DIN) ? W_ih0[gr * DIN + d] : 0.0f;
        }
        if (tid < 32) bs[tid] = b0[grow];
        if (tid < 128) csm[tid] = 0.0f;
        __syncthreads();

        int bp1 = RING - 1;   // backpressure cache vs layer1 consumption of h0 ring

        for (int s = 0; s < T_LEN; ++s) {
            // x prefetch (independent of flags -> hides LDG latency behind poll)
            if (tid < BATCH * DIN) {
                int bb = tid / DIN, d = tid - bb * DIN;
                xs[bb * 8 + d] = __ldg(&x[(bb * T_LEN + s) * DIN + d]);
            }
            if (wrp == 0) {
                if (s > 0) wait32(g_flag0, s);
                if (s > bp1) { int m = wait64min(g_flag1, s - (RING - 1)); bp1 = m + (RING - 1); }
            }
            __syncthreads();

            if (s == 0) {
                for (int i = tid; i < 1024; i += NTHR)
                    *reinterpret_cast<float4*>(hs + i * 4) = make_float4(0.f, 0.f, 0.f, 0.f);
            } else {
                const float4* src = reinterpret_cast<const float4*>(&g_h0[(s - 1) & (RING - 1)][0][0]);
                for (int i = tid; i < 1024; i += NTHR)
                    *reinterpret_cast<float4*>(hs + i * 4) = __ldcg(src + i);
            }
            __syncthreads();

#pragma unroll
            for (int it = 0; it < 4; ++it) {
                int b = bg * 4 + it;
                part[(q * 16 + b) * 33 + r] = dot64_reg(Wreg, hs + b * 256 + q * 64);
            }
            __syncthreads();

            if (tid < 128) {
                int dl = tid >> 4, bb = tid & 15;
                float g4[4];
#pragma unroll
                for (int gate = 0; gate < 4; ++gate) {
                    int rr = gate * 8 + dl;
                    float sum = bs[rr];
#pragma unroll
                    for (int qq = 0; qq < 4; ++qq) sum += part[(qq * 16 + bb) * 33 + rr];
#pragma unroll
                    for (int d = 0; d < DIN; ++d) sum += Wx[rr * 8 + d] * xs[bb * 8 + d];
                    g4[gate] = sum;
                }
                float c  = csm[dl * 16 + bb];
                float cn = sigf(g4[1]) * c + sigf(g4[0]) * tanhfast(g4[2]);
                float hn = sigf(g4[3]) * tanhfast(cn);
                csm[dl * 16 + bb] = cn;
                g_h0[s & (RING - 1)][bb][base + dl] = hn;
                if (s == T_LEN - 1) {
                    out[HN_OFF + bb * HID + base + dl] = hn;
                    out[CN_OFF + bb * HID + base + dl] = cn;
                }
            }
            __syncthreads();
            if (tid == 0) strel(&g_flag0[cta * FPAD], s + 1);
        }
    } else if (cta < NA + NB) {
        // ---------------- Layer 1 CTA: 16 gate rows, K=512, weights in regs ----------------
        float* in_s = smem;                   // [16][520]
        float* part = in_s + 16 * 520;        // [8 q][16 b][17]
        float* gsm2 = part + 8 * 16 * 17;     // [16 b][17]
        float* bs   = gsm2 + 16 * 17;         // [16]
        float* csm  = bs + 16;                // [4][16]
        const int base = (cta - NA) * 4;
        const int q = wrp & 7, bq = wrp >> 3;
        const int r = lane & 15, bh = lane >> 4;
        const int grow = (r >> 2) * 256 + base + (r & 3);

        ull Wreg[32];
        {
            const float* wrow = (q < 4) ? (W_ih1 + grow * 256 + q * 64)
                                        : (W_hh1 + grow * 256 + (q - 4) * 64);
            const float4* wp = reinterpret_cast<const float4*>(wrow);
#pragma unroll
            for (int j = 0; j < 16; ++j) {
                float4 wv = __ldg(wp + j);
                Wreg[2 * j]     = pk2(wv.x, wv.y);
                Wreg[2 * j + 1] = pk2(wv.z, wv.w);
            }
        }
        if (tid < 16) bs[tid] = b1[(tid >> 2) * 256 + base + (tid & 3)];
        if (tid < 64) csm[tid] = 0.0f;
        __syncthreads();

        int bpH = RING - 1;   // backpressure cache vs head consumption of h1 ring

        for (int t1 = 0; t1 < T_LEN; ++t1) {
            if (wrp == 0) {
                if (t1 > 0) wait64(g_flag1, t1);           // peers' h1(t1-1)
                wait32(g_flag0, t1 + 1);                   // h0(t1) available
                if (t1 > bpH) { int m = wait1(g_flagH, t1 - (RING - 1)); bpH = m + (RING - 1); }
            }
            __syncthreads();

            {   // stage [y0(t1) ; h1(t1-1)]
                const float4* src0 = reinterpret_cast<const float4*>(&g_h0[t1 & (RING - 1)][0][0]);
                for (int i = tid; i < 1024; i += NTHR) {
                    int bb = i >> 6, c4 = i & 63;
                    *reinterpret_cast<float4*>(in_s + bb * 520 + c4 * 4) = __ldcg(src0 + i);
                }
                if (t1 == 0) {
                    for (int i = tid; i < 1024; i += NTHR) {
                        int bb = i >> 6, c4 = i & 63;
                        *reinterpret_cast<float4*>(in_s + bb * 520 + 256 + c4 * 4) =
                            make_float4(0.f, 0.f, 0.f, 0.f);
                    }
                } else {
                    const float4* src1 = reinterpret_cast<const float4*>(&g_h1[(t1 - 1) & (RING - 1)][0][0]);
                    for (int i = tid; i < 1024; i += NTHR) {
                        int bb = i >> 6, c4 = i & 63;
                        *reinterpret_cast<float4*>(in_s + bb * 520 + 256 + c4 * 4) = __ldcg(src1 + i);
                    }
                }
            }
            __syncthreads();

#pragma unroll
            for (int it = 0; it < 4; ++it) {
                int b = bq * 8 + it * 2 + bh;
                part[(q * 16 + b) * 17 + r] = dot64_reg(Wreg, in_s + b * 520 + q * 64);
            }
            __syncthreads();

            if (tid < 256) {
                int rr = tid & 15, bb = tid >> 4;
                float sum = bs[rr];
#pragma unroll
                for (int qq = 0; qq < 8; ++qq) sum += part[(qq * 16 + bb) * 17 + rr];
                gsm2[bb * 17 + rr] = sum;
            }
            __syncthreads();

            if (tid < 64) {
                int dl = tid >> 4, bb = tid & 15;
                float iv = gsm2[bb * 17 + dl];
                float fv = gsm2[bb * 17 + 4 + dl];
                float gv = gsm2[bb * 17 + 8 + dl];
                float ov = gsm2[bb * 17 + 12 + dl];
                float c  = csm[dl * 16 + bb];
                float cn = sigf(fv) * c + sigf(iv) * tanhfast(gv);
                float hn = sigf(ov) * tanhfast(cn);
                csm[dl * 16 + bb] = cn;
                g_h1[t1 & (RING - 1)][bb][base + dl] = hn;
                if (t1 == T_LEN - 1) {
                    out[HN_OFF + BATCH * HID + bb * HID + base + dl] = hn;
                    out[CN_OFF + BATCH * HID + bb * HID + base + dl] = cn;
                }
            }
            __syncthreads();
            if (tid == 0) strel(&g_flag1[(cta - NA) * FPAD], t1 + 1);
        }
    } else {
        // ---------------- Head CTA: out_t = W_head @ h1_t + b_head ----------------
        float* Wh  = smem;            // [7][256]
        float* bh  = Wh + 1792;       // [16]
        float* h1s = bh + 16;         // [16][260]

        for (int idx = tid; idx < DIN * 256; idx += NTHR) Wh[idx] = W_head[idx];
        if (tid < DIN) bh[tid] = b_head[tid];
        __syncthreads();

        for (int t = 0; t < T_LEN; ++t) {
            if (wrp == 0) wait64(g_flag1, t + 1);
            __syncthreads();
            const float4* src = reinterpret_cast<const float4*>(&g_h1[t & (RING - 1)][0][0]);
            for (int i = tid; i < 1024; i += NTHR) {
                int bb = i >> 6, c4 = i & 63;
                *reinterpret_cast<float4*>(h1s + bb * 260 + c4 * 4) = __ldcg(src + i);
            }
            __syncthreads();
            if (tid == 0) strel(&g_flagH[0], t + 1);   // h1(t) consumed
            if (tid < BATCH * DIN) {
                int bb = tid / DIN, d = tid - bb * DIN;
                out[(bb * T_LEN + t) * DIN + d] = dot256s(Wh + d * 256, h1s + bb * 260) + bh[d];
            }
        }
    }

    // ---- end-of-run reset: two-phase barrier, each CTA zeroes its own flags ----
    __syncthreads();
    if (tid == 0) {
        __threadfence();
        atomicAdd(&g_bar, 1u);
        unsigned v;
        do { asm volatile("ld.acquire.gpu.u32 %0, [%1];" : "=r"(v) : "l"(&g_bar)); } while (v < GRID_SZ);
        if (cta < NA)            g_flag0[cta * FPAD] = 0;
        else if (cta < NA + NB)  g_flag1[(cta - NA) * FPAD] = 0;
        else                     g_flagH[0] = 0;
        __threadfence();
        atomicAdd(&g_bar, 1u);
        if (cta == 0) {
            do { asm volatile("ld.acquire.gpu.u32 %0, [%1];" : "=r"(v) : "l"(&g_bar)); } while (v < 2u * GRID_SZ);
            atomicExch(&g_bar, 0u);
        }
    }
}

extern "C" void kernel_launch(void* const* d_in, const int* in_sizes, int n_in,
                              void* d_out, int out_size) {
    const float* x      = (const float*)d_in[0];
    const float* W_ih0  = (const float*)d_in[1];
    const float* W_hh0  = (const float*)d_in[2];
    const float* b0     = (const float*)d_in[3];
    const float* W_ih1  = (const float*)d_in[4];
    const float* W_hh1  = (const float*)d_in[5];
    const float* b1     = (const float*)d_in[6];
    const float* W_head = (const float*)d_in[7];
    const float* b_head = (const float*)d_in[8];

    cudaFuncSetAttribute(lstm_persistent_kernel,
                         cudaFuncAttributeMaxDynamicSharedMemorySize, SMEM_BYTES);

    lstm_persistent_kernel<<<GRID_SZ, NTHR, SMEM_BYTES>>>(
        x, W_ih0, W_hh0, b0, W_ih1, W_hh1, b1, W_head, b_head, (float*)d_out);
}

// round 7
// speedup vs baseline: 1.3752x; 1.3087x over previous
#include <cuda_runtime.h>
#include <math.h>

#define T_LEN   8192
#define BATCH   16
#define HID     256
#define DIN     7

#define NA      32            // layer-0 CTAs (8 h-dims -> 32 gate rows each)
#define NB      64            // layer-1 CTAs (4 h-dims -> 16 gate rows each, K=512)
#define GRID_SZ (NA + NB)     // head folded into layer-1 CTAs
#define NTHR    512
#define RING    8
#define FPAD    8             // 32B per flag

#define OUT_ELEMS (BATCH * T_LEN * DIN)
#define HN_OFF    OUT_ELEMS
#define CN_OFF    (OUT_ELEMS + 2 * BATCH * HID)

// layer1 smem: in_s 16*1024 + part 2*2176 + bs 16 + csm 64 + Wh 1792 + bhh 8 = 22616 floats
#define SMEM_BYTES 90464

__device__ unsigned g_bar;
__device__ int g_flag0[NA * FPAD];   // flag0[i] = steps completed by layer0 CTA i
__device__ int g_flag1[NB * FPAD];   // flag1[j] = steps completed by layer1 CTA j
__device__ float g_h0[RING][BATCH][HID];
__device__ float g_h1[RING][BATCH][HID];

typedef unsigned long long ull;

__device__ __forceinline__ ull pk2(float a, float b) {
    ull r; asm("mov.b64 %0, {%1,%2};" : "=l"(r) : "f"(a), "f"(b)); return r;
}
__device__ __forceinline__ void fma2(ull& acc, ull a, ull b) {
    asm("fma.rn.f32x2 %0, %1, %2, %0;" : "+l"(acc) : "l"(a), "l"(b));
}
__device__ __forceinline__ float hsum2(ull a) {
    float x, y; asm("mov.b64 {%0,%1}, %2;" : "=f"(x), "=f"(y) : "l"(a)); return x + y;
}
__device__ __forceinline__ float sigf(float x) {
    return __fdividef(1.0f, 1.0f + __expf(-x));
}
__device__ __forceinline__ float tanhfast(float x) {
    float e = __expf(-2.0f * fabsf(x));
    float t = __fdividef(1.0f - e, 1.0f + e);
    return copysignf(t, x);
}
__device__ __forceinline__ int ldacq(const int* p) {
    int v; asm volatile("ld.acquire.gpu.b32 %0, [%1];" : "=r"(v) : "l"(p) : "memory"); return v;
}
__device__ __forceinline__ void strel(int* p, int v) {
    asm volatile("st.release.gpu.b32 [%0], %1;" :: "l"(p), "r"(v) : "memory");
}

// warp-collective poll of (lane-dependent) flag pointer; p == nullptr lanes idle
__device__ __forceinline__ void poll_warp(const int* p, int target) {
    int v;
    do { v = p ? ldacq(p) : 0x7fffffff; } while (__any_sync(0xffffffffu, v < target));
}
// warp-collective poll of 64 flags, 2 per lane; also returns the min
__device__ __forceinline__ int poll64_min(const int* flags, int target) {
    int lane = threadIdx.x & 31, m;
    const int* p0 = flags + lane * FPAD;
    const int* p1 = flags + (lane + 32) * FPAD;
    do { m = min(ldacq(p0), ldacq(p1)); } while (__any_sync(0xffffffffu, m < target));
    return __reduce_min_sync(0xffffffffu, m);
}

// 64-float dot: weights in regs (32 x f32x2), h from smem broadcast
__device__ __forceinline__ float dot64_reg(const ull* __restrict__ Wreg,
                                           const float* __restrict__ hp) {
    const ulonglong2* h2 = reinterpret_cast<const ulonglong2*>(hp);
    ull a0 = 0ull, a1 = 0ull;
#pragma unroll
    for (int i = 0; i < 16; ++i) {
        ulonglong2 hv = h2[i];
        fma2(a0, Wreg[2 * i],     hv.x);
        fma2(a1, Wreg[2 * i + 1], hv.y);
    }
    return hsum2(a0) + hsum2(a1);
}

extern __shared__ float smem[];

__global__ void __launch_bounds__(NTHR, 1) lstm_persistent_kernel(
    const float* __restrict__ x,
    const float* __restrict__ W_ih0, const float* __restrict__ W_hh0, const float* __restrict__ b0,
    const float* __restrict__ W_ih1, const float* __restrict__ W_hh1, const float* __restrict__ b1,
    const float* __restrict__ W_head, const float* __restrict__ b_head,
    float* __restrict__ out)
{
    const int tid  = threadIdx.x;
    const int cta  = blockIdx.x;
    const int lane = tid & 31;
    const int wrp  = tid >> 5;

    if (cta < NA) {
        // =============== Layer 0 CTA: 32 gate rows, K=256 ===============
        // warp (q = wrp&3 k-quarter, bg = wrp>>2 batch group of 4); lane = gate row.
        float* hs   = smem;                 // per-warp [16 warps][4 b][64] private staging
        float* part = hs + 16 * 256;        // [2 buf][4 q][16 b][33]
        float* Wx   = part + 2 * 2112;      // [32][8]
        float* xs   = Wx + 256;             // [2 buf][16 b][8]
        float* bs   = xs + 256;             // [32]
        float* csm  = bs + 32;              // [8][16]
        const int base = cta * 8;
        const int q = wrp & 3, bg = wrp >> 2;
        const int r = lane;
        const int grow = (r >> 3) * 256 + base + (r & 7);

        ull Wreg[32];
        {
            const float4* wp = reinterpret_cast<const float4*>(W_hh0 + grow * 256 + q * 64);
#pragma unroll
            for (int j = 0; j < 16; ++j) {
                float4 wv = __ldg(wp + j);
                Wreg[2 * j]     = pk2(wv.x, wv.y);
                Wreg[2 * j + 1] = pk2(wv.z, wv.w);
            }
        }
        for (int idx = tid; idx < 32 * 8; idx += NTHR) {
            int rr = idx >> 3, d = idx & 7;
            int gr = (rr >> 3) * 256 + base + (rr & 7);
            Wx[idx] = (d < DIN) ? W_ih0[gr * DIN + d] : 0.0f;
        }
        if (tid < 32) bs[tid] = b0[grow];
        if (tid < 128) csm[tid] = 0.0f;
        __syncthreads();

        float* myh = hs + wrp * 256;
        const int* mypoll = (lane < 8) ? (g_flag0 + (q * 8 + lane) * FPAD) : nullptr;
        int bp1 = RING - 1;   // gate-warp backpressure cache (layer1 consumption)

        for (int s = 0; s < T_LEN; ++s) {
            // x prefetch for step s (warps 12..15 -> 128 threads >= 112 entries)
            if (wrp >= 12) {
                int idx = tid - 384;                  // 0..127
                if (idx < BATCH * DIN) {
                    int bb = idx / DIN, d = idx - bb * DIN;
                    xs[(s & 1) * 128 + bb * 8 + d] = __ldg(&x[(bb * T_LEN + s) * DIN + d]);
                }
            }
            // wait only for this warp's 8 producers
            if (s > 0) poll_warp(mypoll, s);

            // private staging of h[bg*4..+3][q*64..+63]
            if (s == 0) {
#pragma unroll
                for (int j = 0; j < 2; ++j)
                    *reinterpret_cast<float4*>(myh + (lane + 32 * j) * 4) =
                        make_float4(0.f, 0.f, 0.f, 0.f);
            } else {
                const float* srcb = &g_h0[(s - 1) & (RING - 1)][0][0];
#pragma unroll
                for (int j = 0; j < 2; ++j) {
                    int idx = lane + 32 * j;           // 0..63
                    int bl = idx >> 4, c4 = idx & 15;
                    *reinterpret_cast<float4*>(myh + bl * 64 + c4 * 4) =
                        __ldcg(reinterpret_cast<const float4*>(srcb + (bg * 4 + bl) * HID + q * 64) + c4);
                }
            }

            float* pb = part + (s & 1) * 2112;
#pragma unroll
            for (int it = 0; it < 4; ++it)
                pb[(q * 16 + bg * 4 + it) * 33 + r] = dot64_reg(Wreg, myh + it * 64);

            __syncthreads();   // single rendezvous: partials ready

            if (tid < 128) {
                // backpressure: about to overwrite h0(s-8) slot
                if (s > bp1) bp1 = poll64_min(g_flag1, s - (RING - 1)) + (RING - 1);

                int dl = tid >> 4, bb = tid & 15;
                const float* xb = xs + (s & 1) * 128 + bb * 8;
                float g4[4];
#pragma unroll
                for (int gate = 0; gate < 4; ++gate) {
                    int rr = gate * 8 + dl;
                    float sum = bs[rr];
#pragma unroll
                    for (int qq = 0; qq < 4; ++qq) sum += pb[(qq * 16 + bb) * 33 + rr];
#pragma unroll
                    for (int d = 0; d < DIN; ++d) sum += Wx[rr * 8 + d] * xb[d];
                    g4[gate] = sum;
                }
                float c  = csm[dl * 16 + bb];
                float cn = sigf(g4[1]) * c + sigf(g4[0]) * tanhfast(g4[2]);
                float hn = sigf(g4[3]) * tanhfast(cn);
                csm[dl * 16 + bb] = cn;
                g_h0[s & (RING - 1)][bb][base + dl] = hn;
                if (s == T_LEN - 1) {
                    out[HN_OFF + bb * HID + base + dl] = hn;
                    out[CN_OFF + bb * HID + base + dl] = cn;
                }
                asm volatile("bar.sync 1, 128;" ::: "memory");
                if (tid == 0) strel(&g_flag0[cta * FPAD], s + 1);
            }
        }
    } else {
        // =============== Layer 1 CTA: 16 gate rows, K=512, + head share ===============
        // warp (q = wrp&7 k-eighth, bq = wrp>>3); lane: r = lane&15, bh = lane>>4.
        // in_s is double-buffered so head warps can read h1(t1-1) from SMEM post-sync.
        float* in_s = smem;                 // [16 warps][2 buf][512]
        float* part = in_s + 16 * 1024;     // [2 buf][8 q][16 b][17]
        float* bs   = part + 2 * 2176;      // [16]
        float* csm  = bs + 16;              // [4][16]
        float* Wh   = csm + 64;             // [7][256]
        float* bhh  = Wh + 1792;            // [8]
        const int j    = cta - NA;
        const int base = j * 4;
        const int q = wrp & 7, bq = wrp >> 3;
        const int r = lane & 15, bh = lane >> 4;
        const int grow = (r >> 2) * 256 + base + (r & 3);
        const bool is_head = (j < 56) && (wrp >= 14);

        ull Wreg[32];
        {
            const float* wrow = (q < 4) ? (W_ih1 + grow * 256 + q * 64)
                                        : (W_hh1 + grow * 256 + (q - 4) * 64);
            const float4* wp = reinterpret_cast<const float4*>(wrow);
#pragma unroll
            for (int jj = 0; jj < 16; ++jj) {
                float4 wv = __ldg(wp + jj);
                Wreg[2 * jj]     = pk2(wv.x, wv.y);
                Wreg[2 * jj + 1] = pk2(wv.z, wv.w);
            }
        }
        if (tid < 16) bs[tid] = b1[(tid >> 2) * 256 + base + (tid & 3)];
        if (tid < 64) csm[tid] = 0.0f;
        for (int idx = tid; idx < 1792; idx += NTHR) Wh[idx] = W_head[idx];
        if (tid < DIN) bhh[tid] = b_head[tid];
        __syncthreads();

        // poll set: q<4 -> 8 flag0 producers (target t1+1); q>=4 -> 16 flag1 (target t1)
        const int* mypoll;
        if (q < 4)      mypoll = (lane < 8)  ? (g_flag0 + (q * 8 + lane) * FPAD) : nullptr;
        else            mypoll = (lane < 16) ? (g_flag1 + ((q - 4) * 16 + lane) * FPAD) : nullptr;

        for (int t1 = 0; t1 < T_LEN; ++t1) {
            if (is_head) { if (t1 > 0) poll64_min(g_flag1, t1); }
            else if (q < 4) poll_warp(mypoll, t1 + 1);
            else if (t1 > 0) poll_warp(mypoll, t1);

            float* myin = in_s + wrp * 1024 + (t1 & 1) * 512;

            // private staging: q<4 -> y0(t1) chunk; q>=4 -> h1(t1-1) chunk
            if (q >= 4 && t1 == 0) {
#pragma unroll
                for (int jj = 0; jj < 4; ++jj)
                    *reinterpret_cast<float4*>(myin + (lane + 32 * jj) * 4) =
                        make_float4(0.f, 0.f, 0.f, 0.f);
            } else {
                const float* srcb = (q < 4) ? &g_h0[t1 & (RING - 1)][0][0]
                                            : &g_h1[(t1 - 1) & (RING - 1)][0][0];
                int coff = (q < 4) ? q * 64 : (q - 4) * 64;
#pragma unroll
                for (int jj = 0; jj < 4; ++jj) {
                    int idx = lane + 32 * jj;          // 0..127
                    int bl = idx >> 4, c4 = idx & 15;
                    *reinterpret_cast<float4*>(myin + bl * 64 + c4 * 4) =
                        __ldcg(reinterpret_cast<const float4*>(srcb + (bq * 8 + bl) * HID + coff) + c4);
                }
            }

            float* pb = part + (t1 & 1) * 2176;
#pragma unroll
            for (int it = 0; it < 4; ++it) {
                int bl = it * 2 + bh;
                pb[(q * 16 + bq * 8 + bl) * 17 + r] = dot64_reg(Wreg, myin + bl * 64);
            }

            __syncthreads();   // single rendezvous: partials (and h1 staging) ready

            if (tid < 64) {
                int dl = tid >> 4, bb = tid & 15;
                float g4[4];
#pragma unroll
                for (int gate = 0; gate < 4; ++gate) {
                    int rr = gate * 4 + dl;
                    float sum = bs[rr];
#pragma unroll
                    for (int qq = 0; qq < 8; ++qq) sum += pb[(qq * 16 + bb) * 17 + rr];
                    g4[gate] = sum;
                }
                float c  = csm[dl * 16 + bb];
                float cn = sigf(g4[1]) * c + sigf(g4[0]) * tanhfast(g4[2]);
                float hn = sigf(g4[3]) * tanhfast(cn);
                csm[dl * 16 + bb] = cn;
                g_h1[t1 & (RING - 1)][bb][base + dl] = hn;
                if (t1 == T_LEN - 1) {
                    out[HN_OFF + BATCH * HID + bb * HID + base + dl] = hn;
                    out[CN_OFF + BATCH * HID + bb * HID + base + dl] = cn;
                }
                asm volatile("bar.sync 1, 64;" ::: "memory");
                if (tid == 0) strel(&g_flag1[j * FPAD], t1 + 1);
            } else if (is_head && t1 >= 1) {
                // head output for t = t1-1, h1(t1-1) read from warps 8..15's SMEM staging
                int d = j * 2 + (wrp - 14);            // 0..111
                int b = d / 7, dd = d - b * 7;
                // lane covers cols lane*8 .. lane*8+7 = warp q'=4+(lane>>3), inner (lane&7)*8
                const float* hb = in_s + (((b >> 3) * 8 + 4 + (lane >> 3)) * 1024)
                                       + (t1 & 1) * 512 + (b & 7) * 64 + (lane & 7) * 8;
                float4 h0v = *reinterpret_cast<const float4*>(hb);
                float4 h1v = *reinterpret_cast<const float4*>(hb + 4);
                const float4* wp = reinterpret_cast<const float4*>(Wh + dd * 256 + lane * 8);
                float4 w0 = wp[0], w1 = wp[1];
                ull acc = 0ull;
                fma2(acc, pk2(w0.x, w0.y), pk2(h0v.x, h0v.y));
                fma2(acc, pk2(w0.z, w0.w), pk2(h0v.z, h0v.w));
                fma2(acc, pk2(w1.x, w1.y), pk2(h1v.x, h1v.y));
                fma2(acc, pk2(w1.z, w1.w), pk2(h1v.z, h1v.w));
                float v = hsum2(acc);
#pragma unroll
                for (int o = 16; o > 0; o >>= 1) v += __shfl_down_sync(0xffffffffu, v, o);
                if (lane == 0)
                    out[(b * T_LEN + (t1 - 1)) * DIN + dd] = v + bhh[dd];
            }
        }

        // epilogue: head output for t = T_LEN-1 (h1(T_LEN-1) only exists in the global ring)
        if (is_head) {
            poll64_min(g_flag1, T_LEN);
            int d = j * 2 + (wrp - 14);
            int b = d / 7, dd = d - b * 7;
            const float4* hp =
                reinterpret_cast<const float4*>(&g_h1[(T_LEN - 1) & (RING - 1)][b][0]) + lane * 2;
            float4 h0v = __ldcg(hp), h1v = __ldcg(hp + 1);
            const float4* wp = reinterpret_cast<const float4*>(Wh + dd * 256 + lane * 8);
            float4 w0 = wp[0], w1 = wp[1];
            ull acc = 0ull;
            fma2(acc, pk2(w0.x, w0.y), pk2(h0v.x, h0v.y));
            fma2(acc, pk2(w0.z, w0.w), pk2(h0v.z, h0v.w));
            fma2(acc, pk2(w1.x, w1.y), pk2(h1v.x, h1v.y));
            fma2(acc, pk2(w1.z, w1.w), pk2(h1v.z, h1v.w));
            float v = hsum2(acc);
#pragma unroll
            for (int o = 16; o > 0; o >>= 1) v += __shfl_down_sync(0xffffffffu, v, o);
            if (lane == 0)
                out[(b * T_LEN + (T_LEN - 1)) * DIN + dd] = v + bhh[dd];
        }
    }

    // ---- end-of-run reset: two-phase, each CTA zeroes its own flag ----
    __syncthreads();
    if (tid == 0) {
        __threadfence();
        atomicAdd(&g_bar, 1u);
        unsigned v;
        do { asm volatile("ld.acquire.gpu.u32 %0, [%1];" : "=r"(v) : "l"(&g_bar)); } while (v < GRID_SZ);
        if (cta < NA) g_flag0[cta * FPAD] = 0;
        else          g_flag1[(cta - NA) * FPAD] = 0;
        __threadfence();
        atomicAdd(&g_bar, 1u);
        if (cta == 0) {
            do { asm volatile("ld.acquire.gpu.u32 %0, [%1];" : "=r"(v) : "l"(&g_bar)); } while (v < 2u * GRID_SZ);
            atomicExch(&g_bar, 0u);
        }
    }
}

extern "C" void kernel_launch(void* const* d_in, const int* in_sizes, int n_in,
                              void* d_out, int out_size) {
    const float* x      = (const float*)d_in[0];
    const float* W_ih0  = (const float*)d_in[1];
    const float* W_hh0  = (const float*)d_in[2];
    const float* b0     = (const float*)d_in[3];
    const float* W_ih1  = (const float*)d_in[4];
    const float* W_hh1  = (const float*)d_in[5];
    const float* b1     = (const float*)d_in[6];
    const float* W_head = (const float*)d_in[7];
    const float* b_head = (const float*)d_in[8];

    cudaFuncSetAttribute(lstm_persistent_kernel,
                         cudaFuncAttributeMaxDynamicSharedMemorySize, SMEM_BYTES);

    lstm_persistent_kernel<<<GRID_SZ, NTHR, SMEM_BYTES>>>(
        x, W_ih0, W_hh0, b0, W_ih1, W_hh1, b1, W_head, b_head, (float*)d_out);
}

// round 9
// speedup vs baseline: 1.5676x; 1.1399x over previous
#include <cuda_runtime.h>
#include <math.h>

#define T_LEN   8192
#define BATCH   16
#define HID     256
#define DIN     7

#define NG      4              // batch groups (4 batches each) — fully independent machines
#define GB      4              // batches per group
#define NA_G    8              // layer-0 CTAs per group (128 gate rows each)
#define NB_G    16             // layer-1 CTAs per group (64 gate rows each)
#define GRID_SZ (NG * (NA_G + NB_G))   // 96
#define NTHR    512
#define RING    8
#define FPAD    8

#define OUT_ELEMS (BATCH * T_LEN * DIN)
#define HN_OFF    OUT_ELEMS
#define CN_OFF    (OUT_ELEMS + 2 * BATCH * HID)

// layer1 smem: in_s 8192 + part 2*2560 + bs 64 + csm 64 + Wh 1792 + bhh 8 = 15240 floats
#define SMEM_BYTES 60960

__device__ unsigned g_bar;
__device__ int g_flag0[NG * NA_G * FPAD];   // flag = steps completed by that layer-0 CTA
__device__ int g_flag1[NG * NB_G * FPAD];
__device__ float g_h0[NG][RING][GB][HID];
__device__ float g_h1[NG][RING][GB][HID];

typedef unsigned long long ull;

__device__ __forceinline__ ull pk2(float a, float b) {
    ull r; asm("mov.b64 %0, {%1,%2};" : "=l"(r) : "f"(a), "f"(b)); return r;
}
__device__ __forceinline__ void fma2(ull& acc, ull a, ull b) {
    asm("fma.rn.f32x2 %0, %1, %2, %0;" : "+l"(acc) : "l"(a), "l"(b));
}
__device__ __forceinline__ float hsum2(ull a) {
    float x, y; asm("mov.b64 {%0,%1}, %2;" : "=f"(x), "=f"(y) : "l"(a)); return x + y;
}
__device__ __forceinline__ float sigf(float x) {
    return __fdividef(1.0f, 1.0f + __expf(-x));
}
__device__ __forceinline__ float tanhfast(float x) {
    float e = __expf(-2.0f * fabsf(x));
    float t = __fdividef(1.0f - e, 1.0f + e);
    return copysignf(t, x);
}
__device__ __forceinline__ int ldacq(const int* p) {
    int v; asm volatile("ld.acquire.gpu.b32 %0, [%1];" : "=r"(v) : "l"(p) : "memory"); return v;
}
__device__ __forceinline__ void strel(int* p, int v) {
    asm volatile("st.release.gpu.b32 [%0], %1;" :: "l"(p), "r"(v) : "memory");
}

// warp-collective poll; lanes with p==nullptr idle
__device__ __forceinline__ void poll_warp(const int* p, int target) {
    int v;
    do { v = p ? ldacq(p) : 0x7fffffff; } while (__any_sync(0xffffffffu, v < target));
}
// warp-collective poll of 16 flags (lanes 0-15), returns min
__device__ __forceinline__ int poll16_min(const int* flags, int target) {
    int lane = threadIdx.x & 31, m;
    const int* p = (lane < 16) ? (flags + lane * FPAD) : nullptr;
    do { m = p ? ldacq(p) : 0x7fffffff; } while (__any_sync(0xffffffffu, m < target));
    return __reduce_min_sync(0xffffffffu, m);
}

// 64-float dot: weights in regs (32 x f32x2), h from smem broadcast
__device__ __forceinline__ float dot64_reg(const ull* __restrict__ Wreg,
                                           const float* __restrict__ hp) {
    const ulonglong2* h2 = reinterpret_cast<const ulonglong2*>(hp);
    ull a0 = 0ull, a1 = 0ull;
#pragma unroll
    for (int i = 0; i < 16; ++i) {
        ulonglong2 hv = h2[i];
        fma2(a0, Wreg[2 * i],     hv.x);
        fma2(a1, Wreg[2 * i + 1], hv.y);
    }
    return hsum2(a0) + hsum2(a1);
}

// 256-dot for the head: w from smem, h via ptr-indexed smem chunks; warp shfl-reduce
__device__ __forceinline__ float head_dot(const float* __restrict__ Wh, int dd,
                                          const float* h0p) {
    int lane = threadIdx.x & 31;
    float4 h0v = *reinterpret_cast<const float4*>(h0p);
    float4 h1v = *reinterpret_cast<const float4*>(h0p + 4);
    const float4* wp = reinterpret_cast<const float4*>(Wh + dd * 256 + lane * 8);
    float4 w0 = wp[0], w1 = wp[1];
    ull acc = 0ull;
    fma2(acc, pk2(w0.x, w0.y), pk2(h0v.x, h0v.y));
    fma2(acc, pk2(w0.z, w0.w), pk2(h0v.z, h0v.w));
    fma2(acc, pk2(w1.x, w1.y), pk2(h1v.x, h1v.y));
    fma2(acc, pk2(w1.z, w1.w), pk2(h1v.z, h1v.w));
    float v = hsum2(acc);
#pragma unroll
    for (int o = 16; o > 0; o >>= 1) v += __shfl_down_sync(0xffffffffu, v, o);
    return v;
}

extern __shared__ float smem[];

__global__ void __launch_bounds__(NTHR, 1) lstm_persistent_kernel(
    const float* __restrict__ x,
    const float* __restrict__ W_ih0, const float* __restrict__ W_hh0, const float* __restrict__ b0,
    const float* __restrict__ W_ih1, const float* __restrict__ W_hh1, const float* __restrict__ b1,
    const float* __restrict__ W_head, const float* __restrict__ b_head,
    float* __restrict__ out)
{
    const int tid  = threadIdx.x;
    const int cta  = blockIdx.x;
    const int lane = tid & 31;
    const int wrp  = tid >> 5;

    if (cta < NG * NA_G) {
        // =============== Layer 0 CTA: group g, 32 h-dims (128 gate rows), K=256 ===============
        // warp (q = wrp&3 k-quarter, rg = wrp>>2 row-group); lane -> row rg*32+lane.
        const int g = cta >> 3, i = cta & 7;
        float* hs   = smem;                 // [16 warps][4 b][64] private staging
        float* part = hs + 4096;            // [2 buf][4 q][128 r][5]
        float* Wx   = part + 2 * 2560;      // [128][8]
        float* xs   = Wx + 1024;            // [2 buf][4 b][8]
        float* bs   = xs + 64;              // [128]
        float* csm  = bs + 128;             // [32 d][4 b]
        const int q = wrp & 3, rg = wrp >> 2;
        const int r_local = rg * 32 + lane;           // 0..127
        const int grow = (r_local >> 5) * 256 + i * 32 + (r_local & 31);

        ull Wreg[32];
        {
            const float4* wp = reinterpret_cast<const float4*>(W_hh0 + grow * 256 + q * 64);
#pragma unroll
            for (int j = 0; j < 16; ++j) {
                float4 wv = __ldg(wp + j);
                Wreg[2 * j]     = pk2(wv.x, wv.y);
                Wreg[2 * j + 1] = pk2(wv.z, wv.w);
            }
        }
        for (int idx = tid; idx < 128 * 8; idx += NTHR) {
            int rr = idx >> 3, d = idx & 7;
            int gr = (rr >> 5) * 256 + i * 32 + (rr & 31);
            Wx[idx] = (d < DIN) ? W_ih0[gr * DIN + d] : 0.0f;
        }
        // FIX (R8 bug): explicit gate-row formula — tid<128 threads all have rg=0,
        // so b0[grow] would replicate gate-0 biases across all four gates.
        if (tid < 128) bs[tid] = b0[(tid >> 5) * 256 + i * 32 + (tid & 31)];
        if (tid < 128) csm[tid] = 0.0f;
        __syncthreads();

        float* myh = hs + wrp * 256;
        const int* mypoll = (lane < 2) ? (g_flag0 + (g * 8 + q * 2 + lane) * FPAD) : nullptr;
        int bp1 = RING - 1;

        for (int s = 0; s < T_LEN; ++s) {
            // x prefetch (warp 15, 28 values), before any waiting
            if (wrp == 15 && lane < GB * DIN) {
                int bb = lane / DIN, d = lane - bb * DIN;
                xs[(s & 1) * 32 + bb * 8 + d] = __ldg(&x[((g * 4 + bb) * T_LEN + s) * DIN + d]);
            }
            if (s > 0) poll_warp(mypoll, s);          // 2 producers own this k-chunk

            // private staging of h[0..3][q*64..+63]
            if (s == 0) {
#pragma unroll
                for (int j = 0; j < 2; ++j)
                    *reinterpret_cast<float4*>(myh + (lane + 32 * j) * 4) =
                        make_float4(0.f, 0.f, 0.f, 0.f);
            } else {
                const float4* srcb = reinterpret_cast<const float4*>(&g_h0[g][(s - 1) & (RING - 1)][0][0]);
#pragma unroll
                for (int j = 0; j < 2; ++j) {
                    int idx = lane + 32 * j;           // 0..63
                    int bl = idx >> 4, c4 = idx & 15;
                    *reinterpret_cast<float4*>(myh + bl * 64 + c4 * 4) =
                        __ldcg(srcb + bl * 64 + q * 16 + c4);
                }
            }

            float* pb = part + (s & 1) * 2560;
#pragma unroll
            for (int it = 0; it < 4; ++it)
                pb[(q * 128 + r_local) * 5 + it] = dot64_reg(Wreg, myh + it * 64);

            __syncthreads();

            if (tid < 128) {
                if (s > bp1) bp1 = poll16_min(g_flag1 + g * 16 * FPAD, s - (RING - 1)) + (RING - 1);

                int d = tid & 31, bb = tid >> 5;
                const float* xb = xs + (s & 1) * 32 + bb * 8;
                float g4[4];
#pragma unroll
                for (int gate = 0; gate < 4; ++gate) {
                    int rr = gate * 32 + d;
                    float sum = bs[rr];
#pragma unroll
                    for (int qq = 0; qq < 4; ++qq) sum += pb[(qq * 128 + rr) * 5 + bb];
#pragma unroll
                    for (int dd = 0; dd < DIN; ++dd) sum += Wx[rr * 8 + dd] * xb[dd];
                    g4[gate] = sum;
                }
                float c  = csm[d * 4 + bb];
                float cn = sigf(g4[1]) * c + sigf(g4[0]) * tanhfast(g4[2]);
                float hn = sigf(g4[3]) * tanhfast(cn);
                csm[d * 4 + bb] = cn;
                g_h0[g][s & (RING - 1)][bb][i * 32 + d] = hn;
                if (s == T_LEN - 1) {
                    out[HN_OFF + (g * 4 + bb) * HID + i * 32 + d] = hn;
                    out[CN_OFF + (g * 4 + bb) * HID + i * 32 + d] = cn;
                }
                asm volatile("bar.sync 1, 128;" ::: "memory");
                if (tid == 0) strel(&g_flag0[(g * 8 + i) * FPAD], s + 1);
            }
        }
    } else {
        // =============== Layer 1 CTA: group g, 16 h-dims (64 gate rows), K=512, + head ===============
        // warp (q = wrp&7 k-eighth, rh = wrp>>3); lane -> row rh*32+lane.
        const int c2 = cta - NG * NA_G;
        const int g = c2 >> 4, j = c2 & 15;
        float* in_s = smem;                 // [16 warps][2 buf][4 b][64]
        float* part = in_s + 8192;          // [2 buf][8 q][64 r][5]
        float* bs   = part + 2 * 2560;      // [64]
        float* csm  = bs + 64;              // [16 d][4 b]
        float* Wh   = csm + 64;             // [7][256]
        float* bhh  = Wh + 1792;            // [8]
        const int q = wrp & 7, rh = wrp >> 3;
        const int r_local = rh * 32 + lane;            // 0..63
        const int grow = (r_local >> 4) * 256 + j * 16 + (r_local & 15);
        const int hd = j * 2 + (wrp - 14);             // head duty index (warps 14,15)
        const bool is_head = (wrp >= 14) && (hd < GB * DIN);

        ull Wreg[32];
        {
            const float* wrow = (q < 4) ? (W_ih1 + grow * 256 + q * 64)
                                        : (W_hh1 + grow * 256 + (q - 4) * 64);
            const float4* wp = reinterpret_cast<const float4*>(wrow);
#pragma unroll
            for (int jj = 0; jj < 16; ++jj) {
                float4 wv = __ldg(wp + jj);
                Wreg[2 * jj]     = pk2(wv.x, wv.y);
                Wreg[2 * jj + 1] = pk2(wv.z, wv.w);
            }
        }
        if (tid < 64) bs[tid] = b1[(tid >> 4) * 256 + j * 16 + (tid & 15)];
        if (tid < 64) csm[tid] = 0.0f;
        for (int idx = tid; idx < 1792; idx += NTHR) Wh[idx] = W_head[idx];
        if (tid < DIN) bhh[tid] = b_head[tid];
        __syncthreads();

        // poll set: q<4 -> 2 flag0 (target t+1); q>=4 -> 4 flag1 (target t)
        const int* mypoll;
        if (q < 4) mypoll = (lane < 2) ? (g_flag0 + (g * 8 + q * 2 + lane) * FPAD) : nullptr;
        else       mypoll = (lane < 4) ? (g_flag1 + (g * 16 + (q - 4) * 4 + lane) * FPAD) : nullptr;

        const int hb = is_head ? (hd / DIN) : 0;            // head batch (local)
        const int hdd = is_head ? (hd - hb * DIN) : 0;      // head out dim
        // head reads h1(t-1) from warps q'=4+(lane>>3) (rh=0) private staging
        const float* headsrc = in_s + (4 + (lane >> 3)) * 512 + hb * 64 + (lane & 7) * 8;

        for (int t = 0; t < T_LEN; ++t) {
            if (q < 4) poll_warp(mypoll, t + 1);
            else if (t > 0) poll_warp(mypoll, t);

            float* myin = in_s + wrp * 512 + (t & 1) * 256;

            if (q >= 4 && t == 0) {
#pragma unroll
                for (int jj = 0; jj < 2; ++jj)
                    *reinterpret_cast<float4*>(myin + (lane + 32 * jj) * 4) =
                        make_float4(0.f, 0.f, 0.f, 0.f);
            } else {
                const float4* srcb = (q < 4)
                    ? reinterpret_cast<const float4*>(&g_h0[g][t & (RING - 1)][0][0])
                    : reinterpret_cast<const float4*>(&g_h1[g][(t - 1) & (RING - 1)][0][0]);
                int coff = (q < 4) ? q * 16 : (q - 4) * 16;   // float4 units
#pragma unroll
                for (int jj = 0; jj < 2; ++jj) {
                    int idx = lane + 32 * jj;          // 0..63
                    int bl = idx >> 4, c4 = idx & 15;
                    *reinterpret_cast<float4*>(myin + bl * 64 + c4 * 4) =
                        __ldcg(srcb + bl * 64 + coff + c4);
                }
            }

            float* pb = part + (t & 1) * 2560;
#pragma unroll
            for (int it = 0; it < 4; ++it)
                pb[(q * 64 + r_local) * 5 + it] = dot64_reg(Wreg, myin + it * 64);

            __syncthreads();

            if (tid < 64) {
                int d = tid & 15, bb = tid >> 4;
                float g4[4];
#pragma unroll
                for (int gate = 0; gate < 4; ++gate) {
                    int rr = gate * 16 + d;
                    float sum = bs[rr];
#pragma unroll
                    for (int qq = 0; qq < 8; ++qq) sum += pb[(qq * 64 + rr) * 5 + bb];
                    g4[gate] = sum;
                }
                float c  = csm[d * 4 + bb];
                float cn = sigf(g4[1]) * c + sigf(g4[0]) * tanhfast(g4[2]);
                float hn = sigf(g4[3]) * tanhfast(cn);
                csm[d * 4 + bb] = cn;
                g_h1[g][t & (RING - 1)][bb][j * 16 + d] = hn;
                if (t == T_LEN - 1) {
                    out[HN_OFF + BATCH * HID + (g * 4 + bb) * HID + j * 16 + d] = hn;
                    out[CN_OFF + BATCH * HID + (g * 4 + bb) * HID + j * 16 + d] = cn;
                }
                asm volatile("bar.sync 1, 64;" ::: "memory");
                if (tid == 0) strel(&g_flag1[(g * 16 + j) * FPAD], t + 1);
            } else if (is_head && t >= 1) {
                // out(t-1) from h1(t-1), staged in own CTA's smem this step (buffer t&1)
                float v = head_dot(Wh, hdd, headsrc + (t & 1) * 256);
                if (lane == 0)
                    out[((g * 4 + hb) * T_LEN + (t - 1)) * DIN + hdd] = v + bhh[hdd];
            }
        }

        // epilogue: out(T-1) — h1(T-1) only in the global ring
        if (is_head) {
            poll16_min(g_flag1 + g * 16 * FPAD, T_LEN);
            float hreg[8];
            const float4* hp = reinterpret_cast<const float4*>(
                &g_h1[g][(T_LEN - 1) & (RING - 1)][hb][0]) + lane * 2;
            *reinterpret_cast<float4*>(hreg)     = __ldcg(hp);
            *reinterpret_cast<float4*>(hreg + 4) = __ldcg(hp + 1);
            float v = head_dot(Wh, hdd, hreg);
            if (lane == 0)
                out[((g * 4 + hb) * T_LEN + (T_LEN - 1)) * DIN + hdd] = v + bhh[hdd];
        }
    }

    // ---- end-of-run reset: two-phase, each CTA zeroes its own flag ----
    __syncthreads();
    if (tid == 0) {
        __threadfence();
        atomicAdd(&g_bar, 1u);
        unsigned v;
        do { asm volatile("ld.acquire.gpu.u32 %0, [%1];" : "=r"(v) : "l"(&g_bar)); } while (v < GRID_SZ);
        if (cta < NG * NA_G) g_flag0[cta * FPAD] = 0;
        else                 g_flag1[(cta - NG * NA_G) * FPAD] = 0;
        __threadfence();
        atomicAdd(&g_bar, 1u);
        if (cta == 0) {
            do { asm volatile("ld.acquire.gpu.u32 %0, [%1];" : "=r"(v) : "l"(&g_bar)); } while (v < 2u * GRID_SZ);
            atomicExch(&g_bar, 0u);
        }
    }
}

extern "C" void kernel_launch(void* const* d_in, const int* in_sizes, int n_in,
                              void* d_out, int out_size) {
    const float* x      = (const float*)d_in[0];
    const float* W_ih0  = (const float*)d_in[1];
    const float* W_hh0  = (const float*)d_in[2];
    const float* b0     = (const float*)d_in[3];
    const float* W_ih1  = (const float*)d_in[4];
    const float* W_hh1  = (const float*)d_in[5];
    const float* b1     = (const float*)d_in[6];
    const float* W_head = (const float*)d_in[7];
    const float* b_head = (const float*)d_in[8];

    cudaFuncSetAttribute(lstm_persistent_kernel,
                         cudaFuncAttributeMaxDynamicSharedMemorySize, SMEM_BYTES);

    lstm_persistent_kernel<<<GRID_SZ, NTHR, SMEM_BYTES>>>(
        x, W_ih0, W_hh0, b0, W_ih1, W_hh1, b1, W_head, b_head, (float*)d_out);
}